// round 8
// baseline (speedup 1.0000x reference)
#include <cuda_runtime.h>

// ---------------------------------------------------------------------------
// FrontierLayerVN fused kernel, v8:
//   - 16 warps/SM persistent (4/SMSP), R=8 rows per warp, regs capped at 128
//   - stage B j-split into two passes (ps[8] instead of ps[16]); gate + partB
//     folded per pass so s1 never needs 32 live registers
//   - gate operands staged [jpos][4rows] -> LDS.128 gives row-pair f32x2
//     operands with zero packing
//   - scratch 288 floats/warp: stage A in 4-row halves, D/E/F per 2-row group
//   - smem total unchanged: 232192 B
// ---------------------------------------------------------------------------

#define NWARPS 16
#define THREADS (NWARPS * 32)
#define FULLMASK 0xffffffffu

#define SZ_WV11 4096   // 64x64
#define SZ_WV21 2048   // 64x32 (interleaved-transposed)
#define SZ_WS1  40960  // 320x128
#define SZ_WG1  4096   // 128x32 (interleaved-transposed)
#define SZ_BG1  32
#define SZ_WD1  1024   // 32x32 (interleaved-transposed)
#define SZ_WV12 1024   // 32x32 (interleaved-transposed)
#define SZ_WS2  160
#define SZ_WEIGHTS (SZ_WV11 + SZ_WV21 + SZ_WS1 + SZ_WG1 + SZ_BG1 + SZ_WD1 + SZ_WV12 + SZ_WS2)
#define WS_FLOATS 288
#define SMEM_FLOATS (SZ_WEIGHTS + NWARPS * WS_FLOATS)   // 58048 floats = 232192 B

typedef unsigned long long u64;

__device__ __forceinline__ u64 pk2(float x, float y) {
    u64 d; asm("mov.b64 %0, {%1, %2};" : "=l"(d) : "f"(x), "f"(y)); return d;
}
__device__ __forceinline__ void upk2(float& x, float& y, u64 d) {
    asm("mov.b64 {%0, %1}, %2;" : "=f"(x), "=f"(y) : "l"(d));
}
__device__ __forceinline__ void fma2(u64& a, u64 x, u64 w) {
    asm("fma.rn.f32x2 %0, %1, %2, %3;" : "=l"(a) : "l"(x), "l"(w), "l"(a));
}
__device__ __forceinline__ float fcomp(const float4& v, int e) {
    return (&v.x)[e];   // e compile-time under #pragma unroll
}

// stage-B inner loop over a staged 32-k chunk ([r][32] floats), j-split:
// lane accumulates j = 4*lane + 2*jh + {0,1} into ps[r] (f32x2 pair).
__device__ __forceinline__ void b_chunk_h(
    u64* __restrict__ ps,
    const float* __restrict__ ws, const float* __restrict__ sWs1,
    int k_base, int lane, int jh)
{
    const float4* wsv4 = (const float4*)ws;
    const int woff = 4*lane + 2*jh;
    for (int kq = 0; kq < 8; kq++) {
        float4 xs[8];
        #pragma unroll
        for (int r = 0; r < 8; r++) xs[r] = wsv4[r*8 + kq];
        #pragma unroll
        for (int e = 0; e < 4; e++) {
            int k = k_base + kq*4 + e;
            float2 w2 = *(const float2*)(sWs1 + k*128 + woff);
            u64 wa = pk2(w2.x, w2.y);
            #pragma unroll
            for (int r = 0; r < 8; r++) {
                float x = fcomp(xs[r], e);
                fma2(ps[r], pk2(x, x), wa);
            }
        }
    }
}

__global__ __launch_bounds__(THREADS, 1)
void frontier_vn_kernel(
    const float* __restrict__ g_sca,   // (N,256)
    const float* __restrict__ g_vec,   // (N,64,3)
    const int*   __restrict__ g_idx,   // (M,)
    const float* __restrict__ gWv11,   // (64,64)
    const float* __restrict__ gWv21,   // (64,32)
    const float* __restrict__ gWs1,    // (320,128)
    const float* __restrict__ gWg1,    // (128,32)
    const float* __restrict__ gbg1,    // (32,)
    const float* __restrict__ gWd1,    // (32,32)
    const float* __restrict__ gWv12,   // (32,32)
    const float* __restrict__ gWs2,    // (160,)
    float* __restrict__ out,           // (M,)
    int M)
{
    extern __shared__ float sm[];
    float* sWv11 = sm;
    float* sWv21 = sWv11 + SZ_WV11;   // interleaved-transposed
    float* sWs1  = sWv21 + SZ_WV21;
    float* sWg1  = sWs1  + SZ_WS1;    // interleaved-transposed
    float* sbg1  = sWg1  + SZ_WG1;
    float* sWd1  = sbg1  + SZ_BG1;    // interleaved-transposed
    float* sWv12 = sWd1  + SZ_WD1;    // interleaved-transposed
    float* sWs2  = sWv12 + SZ_WV12;
    float* scratch = sWs2 + SZ_WS2;

    const int tid = threadIdx.x;

    // ---- cooperative weight staging ----
    {
        const float4* s; float4* d;
        d = (float4*)sWv11; s = (const float4*)gWv11;
        for (int i = tid; i < SZ_WV11/4; i += THREADS) d[i] = s[i];
        d = (float4*)sWs1;  s = (const float4*)gWs1;
        for (int i = tid; i < SZ_WS1/4;  i += THREADS) d[i] = s[i];
        d = (float4*)sbg1;  s = (const float4*)gbg1;
        for (int i = tid; i < SZ_BG1/4;  i += THREADS) d[i] = s[i];
        d = (float4*)sWs2;  s = (const float4*)gWs2;
        for (int i = tid; i < SZ_WS2/4;  i += THREADS) d[i] = s[i];
        // interleaved-transposed: (k,o) of (K,32) -> float idx (k>>2)*128 + o*4 + (k&3)
        for (int i = tid; i < SZ_WG1; i += THREADS) {
            int k = i >> 5, o = i & 31;
            sWg1[(k >> 2)*128 + (o << 2) + (k & 3)] = gWg1[i];
        }
        for (int i = tid; i < SZ_WV21; i += THREADS) {
            int k = i >> 5, o = i & 31;
            sWv21[(k >> 2)*128 + (o << 2) + (k & 3)] = gWv21[i];
        }
        for (int i = tid; i < SZ_WD1; i += THREADS) {
            int k = i >> 5, o = i & 31;
            sWd1[(k >> 2)*128 + (o << 2) + (k & 3)] = gWd1[i];
        }
        for (int i = tid; i < SZ_WV12; i += THREADS) {
            int k = i >> 5, o = i & 31;
            sWv12[(k >> 2)*128 + (o << 2) + (k & 3)] = gWv12[i];
        }
    }
    __syncthreads();

    const int warp = tid >> 5;
    const int lane = tid & 31;
    float* ws = scratch + warp * WS_FLOATS;
    float4* wsv4 = (float4*)ws;

    const float2* sWv11_f2 = (const float2*)sWv11;
    const float4* sWv21_f4 = (const float4*)sWv21;
    const float4* sWd1_f4  = (const float4*)sWd1;
    const float4* sWv12_f4 = (const float4*)sWv12;
    const float4* g_sca4   = (const float4*)g_sca;
    const float4* g_vec4   = (const float4*)g_vec;

    const int r_ln = lane >> 2;      // 0..7 (sca gather row)
    const int q_ln = lane & 3;
    const int rA   = lane >> 3;      // 0..3 (vec gather row within half)
    const int iA   = lane & 7;       // 0..7

    const float w2head = sWs2[lane];

    for (int base = (blockIdx.x * NWARPS + warp) * 8; base < M;
         base += gridDim.x * NWARPS * 8)
    {
        int ma = base + rA;           if (ma >= M) ma = M - 1;
        int mb = base + 4 + rA;       if (mb >= M) mb = M - 1;
        int md = base + r_ln;         if (md >= M) md = M - 1;
        const int idx_a = g_idx[ma];
        const int idx_b = g_idx[mb];
        const int idx_d = g_idx[md];
        const size_t sbase = (size_t)idx_d * 64;   // f4 units

        // =================== Stage A: vec -> vh (4-row halves) ==============
        u64 pax[8], pay[8], paz[8];
        #pragma unroll
        for (int r = 0; r < 8; r++) { pax[r]=0ull; pay[r]=0ull; paz[r]=0ull; }

        // prefetch s=0 (chunk 0, half 0)
        float4 t0, t1;
        {
            size_t vb = (size_t)idx_a * 48;
            t0 = g_vec4[vb + iA];
            t1 = (iA < 4) ? g_vec4[vb + 8 + iA] : make_float4(0,0,0,0);
        }
        for (int s = 0; s < 8; s++) {
            const int half = s & 1, chunk = s >> 1;
            __syncwarp();
            wsv4[rA*12 + iA] = t0;
            if (iA < 4) wsv4[rA*12 + 8 + iA] = t1;
            if (s < 7) {
                int nh = (s+1) & 1, nc = (s+1) >> 1;
                size_t vb = (size_t)(nh ? idx_b : idx_a) * 48 + nc*12;
                t0 = g_vec4[vb + iA];
                if (iA < 4) t1 = g_vec4[vb + 8 + iA];
            }
            __syncwarp();
            for (int cq = 0; cq < 4; cq++) {
                u64 ww[4];
                #pragma unroll
                for (int e = 0; e < 4; e++) {
                    float2 w2 = sWv11_f2[(chunk*16 + cq*4 + e)*32 + lane];
                    ww[e] = pk2(w2.x, w2.y);
                }
                #pragma unroll
                for (int r2 = 0; r2 < 4; r2++) {
                    float4 f0 = wsv4[r2*12 + 3*cq + 0];
                    float4 f1 = wsv4[r2*12 + 3*cq + 1];
                    float4 f2 = wsv4[r2*12 + 3*cq + 2];
                    float vcx[4] = {f0.x, f0.w, f1.z, f2.y};
                    float vcy[4] = {f0.y, f1.x, f1.w, f2.z};
                    float vcz[4] = {f0.z, f1.y, f2.x, f2.w};
                    int r = half*4 + r2;
                    #pragma unroll
                    for (int e = 0; e < 4; e++) {
                        fma2(pax[r], pk2(vcx[e], vcx[e]), ww[e]);
                        fma2(pay[r], pk2(vcy[e], vcy[e]), ww[e]);
                        fma2(paz[r], pk2(vcz[e], vcz[e]), ww[e]);
                    }
                }
            }
        }

        // =================== Stage B + C: two j-passes ======================
        float partB[8];
        #pragma unroll
        for (int r = 0; r < 8; r++) partB[r] = 0.f;
        u64 gg01[2] = {0ull, 0ull};   // rows (p*4+0, p*4+1)
        u64 gg23[2] = {0ull, 0ull};   // rows (p*4+2, p*4+3)

        #pragma unroll
        for (int jh = 0; jh < 2; jh++) {
            u64 ps[8];
            #pragma unroll
            for (int r = 0; r < 8; r++) ps[r] = 0ull;

            float4 sf0 = g_sca4[sbase + q_ln];
            float4 sf1 = g_sca4[sbase + q_ln + 4];

            // vn chunks: k=h in [0,64)
            #pragma unroll
            for (int chunk = 0; chunk < 2; chunk++) {
                __syncwarp();
                if ((lane >> 4) == chunk) {
                    int klocal = 2*lane - 32*chunk;   // even, 0..30
                    #pragma unroll
                    for (int r = 0; r < 8; r++) {
                        float x0,x1,y0,y1,z0,z1;
                        upk2(x0,x1,pax[r]); upk2(y0,y1,pay[r]); upk2(z0,z1,paz[r]);
                        ws[r*32 + klocal]     = sqrtf(x0*x0 + y0*y0 + z0*z0);
                        ws[r*32 + klocal + 1] = sqrtf(x1*x1 + y1*y1 + z1*z1);
                    }
                }
                __syncwarp();
                b_chunk_h(ps, ws, sWs1, chunk*32, lane, jh);
            }
            // sca passes: k in [64,320)
            for (int pass = 0; pass < 8; pass++) {
                __syncwarp();
                wsv4[r_ln*8 + q_ln]     = sf0;
                wsv4[r_ln*8 + 4 + q_ln] = sf1;
                if (pass < 7) {
                    sf0 = g_sca4[sbase + (pass+1)*8 + q_ln];
                    sf1 = g_sca4[sbase + (pass+1)*8 + q_ln + 4];
                }
                __syncwarp();
                b_chunk_h(ps, ws, sWs1, 64 + pass*32, lane, jh);
            }

            // partB fold for this pass's two j columns
            {
                float2 w2t = *(const float2*)(sWs2 + 32 + 4*lane + 2*jh);
                #pragma unroll
                for (int r = 0; r < 8; r++) {
                    float s0, s1v;
                    upk2(s0, s1v, ps[r]);
                    partB[r] += ((s0  >= 0.f) ? s0  : 0.01f*s0)  * w2t.x
                              + ((s1v >= 0.f) ? s1v : 0.01f*s1v) * w2t.y;
                }
            }

            // gate partial: stage s1-subset [jpos][4rows], accumulate
            #pragma unroll
            for (int p = 0; p < 2; p++) {
                __syncwarp();
                #pragma unroll
                for (int r2 = 0; r2 < 4; r2++) {
                    float s0, s1v;
                    upk2(s0, s1v, ps[p*4 + r2]);
                    ws[(2*lane)*4 + r2]     = s0;
                    ws[(2*lane + 1)*4 + r2] = s1v;
                }
                __syncwarp();
                const ulonglong2* xpt = (const ulonglong2*)ws;
                for (int u = 0; u < 32; u++) {
                    float2 w2 = *(const float2*)(sWg1 + u*128 + 4*lane + 2*jh);
                    u64 wA = pk2(w2.x, w2.x);
                    u64 wB = pk2(w2.y, w2.y);
                    ulonglong2 xa = xpt[2*u];       // jpos 2u: rows 01, 23
                    ulonglong2 xb = xpt[2*u + 1];   // jpos 2u+1
                    fma2(gg01[p], xa.x, wA); fma2(gg23[p], xa.y, wA);
                    fma2(gg01[p], xb.x, wB); fma2(gg23[p], xb.y, wB);
                }
            }
        }

        // sigmoid
        float ggf[8];
        {
            float bias = sbg1[lane];
            #pragma unroll
            for (int p = 0; p < 2; p++) {
                float a,b,c,d;
                upk2(a,b,gg01[p]); upk2(c,d,gg23[p]);
                ggf[p*4+0] = 1.f / (1.f + __expf(-(a + bias)));
                ggf[p*4+1] = 1.f / (1.f + __expf(-(b + bias)));
                ggf[p*4+2] = 1.f / (1.f + __expf(-(c + bias)));
                ggf[p*4+3] = 1.f / (1.f + __expf(-(d + bias)));
            }
        }

        // =================== D/E/F per 2-row group ==========================
        #pragma unroll
        for (int g = 0; g < 4; g++) {
            // ---- D: out_vec ----
            u64 oxy[2] = {0ull, 0ull};
            float ozv[2] = {0.f, 0.f};
            #pragma unroll
            for (int t = 0; t < 2; t++) {
                __syncwarp();
                if ((lane >> 4) == t) {
                    int h0 = 2*lane - 32*t;
                    #pragma unroll
                    for (int rr = 0; rr < 2; rr++) {
                        int r = 2*g + rr;
                        *(u64*)(ws + rr*96 +  0 + h0) = pax[r];
                        *(u64*)(ws + rr*96 + 32 + h0) = pay[r];
                        *(u64*)(ws + rr*96 + 64 + h0) = paz[r];
                    }
                }
                __syncwarp();
                for (int hq = 0; hq < 8; hq++) {
                    float4 xv[2][3];
                    #pragma unroll
                    for (int rr = 0; rr < 2; rr++) {
                        xv[rr][0] = wsv4[rr*24 + 0*8 + hq];
                        xv[rr][1] = wsv4[rr*24 + 1*8 + hq];
                        xv[rr][2] = wsv4[rr*24 + 2*8 + hq];
                    }
                    float4 w4 = sWv21_f4[(t*8 + hq)*32 + lane];
                    #pragma unroll
                    for (int e = 0; e < 4; e++) {
                        float w = fcomp(w4, e);
                        u64 ww = pk2(w, w);
                        #pragma unroll
                        for (int rr = 0; rr < 2; rr++) {
                            fma2(oxy[rr], pk2(fcomp(xv[rr][0],e), fcomp(xv[rr][1],e)), ww);
                            ozv[rr] += w * fcomp(xv[rr][2], e);
                        }
                    }
                }
            }
            float v2x[2], v2y[2], v2z[2];
            #pragma unroll
            for (int rr = 0; rr < 2; rr++) {
                float ox, oy; upk2(ox, oy, oxy[rr]);
                float gv = ggf[2*g + rr];
                v2x[rr] = gv*ox; v2y[rr] = gv*oy; v2z[rr] = gv*ozv[rr];
            }

            // ---- E: VNLeakyReLU ----
            __syncwarp();
            #pragma unroll
            for (int rr = 0; rr < 2; rr++) {
                ws[rr*96 +  0 + lane] = v2x[rr];
                ws[rr*96 + 32 + lane] = v2y[rr];
                ws[rr*96 + 64 + lane] = v2z[rr];
            }
            __syncwarp();
            u64 dxy[2] = {0ull, 0ull};
            float dzv[2] = {0.f, 0.f};
            for (int cq = 0; cq < 8; cq++) {
                float4 xv[2][3];
                #pragma unroll
                for (int rr = 0; rr < 2; rr++) {
                    xv[rr][0] = wsv4[rr*24 + 0*8 + cq];
                    xv[rr][1] = wsv4[rr*24 + 1*8 + cq];
                    xv[rr][2] = wsv4[rr*24 + 2*8 + cq];
                }
                float4 w4 = sWd1_f4[cq*32 + lane];
                #pragma unroll
                for (int e = 0; e < 4; e++) {
                    float w = fcomp(w4, e);
                    u64 ww = pk2(w, w);
                    #pragma unroll
                    for (int rr = 0; rr < 2; rr++) {
                        fma2(dxy[rr], pk2(fcomp(xv[rr][0],e), fcomp(xv[rr][1],e)), ww);
                        dzv[rr] += w * fcomp(xv[rr][2], e);
                    }
                }
            }
            float v3x[2], v3y[2], v3z[2];
            #pragma unroll
            for (int rr = 0; rr < 2; rr++) {
                float dx, dy; upk2(dx, dy, dxy[rr]);
                float dz = dzv[rr];
                float dot = v2x[rr]*dx + v2y[rr]*dy + v2z[rr]*dz;
                float dsq = dx*dx + dy*dy + dz*dz;
                float tt  = dot / (dsq + 1e-6f);
                float rx = (dot >= 0.f) ? v2x[rr] : (v2x[rr] - tt*dx);
                float ry = (dot >= 0.f) ? v2y[rr] : (v2y[rr] - tt*dy);
                float rz = (dot >= 0.f) ? v2z[rr] : (v2z[rr] - tt*dz);
                v3x[rr] = 0.2f*v2x[rr] + 0.8f*rx;
                v3y[rr] = 0.2f*v2y[rr] + 0.8f*ry;
                v3z[rr] = 0.2f*v2z[rr] + 0.8f*rz;
            }

            // ---- F: layer 2 + output ----
            __syncwarp();
            #pragma unroll
            for (int rr = 0; rr < 2; rr++) {
                ws[rr*96 +  0 + lane] = v3x[rr];
                ws[rr*96 + 32 + lane] = v3y[rr];
                ws[rr*96 + 64 + lane] = v3z[rr];
            }
            __syncwarp();
            u64 bxy[2] = {0ull, 0ull};
            float bzv[2] = {0.f, 0.f};
            for (int cq = 0; cq < 8; cq++) {
                float4 xv[2][3];
                #pragma unroll
                for (int rr = 0; rr < 2; rr++) {
                    xv[rr][0] = wsv4[rr*24 + 0*8 + cq];
                    xv[rr][1] = wsv4[rr*24 + 1*8 + cq];
                    xv[rr][2] = wsv4[rr*24 + 2*8 + cq];
                }
                float4 w4 = sWv12_f4[cq*32 + lane];
                #pragma unroll
                for (int e = 0; e < 4; e++) {
                    float w = fcomp(w4, e);
                    u64 ww = pk2(w, w);
                    #pragma unroll
                    for (int rr = 0; rr < 2; rr++) {
                        fma2(bxy[rr], pk2(fcomp(xv[rr][0],e), fcomp(xv[rr][1],e)), ww);
                        bzv[rr] += w * fcomp(xv[rr][2], e);
                    }
                }
            }
            #pragma unroll
            for (int rr = 0; rr < 2; rr++) {
                float bx, by; upk2(bx, by, bxy[rr]);
                float bz = bzv[rr];
                float vn2 = sqrtf(bx*bx + by*by + bz*bz);
                float pp = vn2 * w2head + partB[2*g + rr];
                #pragma unroll
                for (int off = 16; off > 0; off >>= 1)
                    pp += __shfl_xor_sync(FULLMASK, pp, off);
                if (lane == 0) {
                    int m = base + 2*g + rr;
                    if (m < M) out[m] = pp;
                }
            }
        }
        __syncwarp();
    }
}

extern "C" void kernel_launch(void* const* d_in, const int* in_sizes, int n_in,
                              void* d_out, int out_size)
{
    const float* g_sca  = (const float*)d_in[0];
    const float* g_vec  = (const float*)d_in[1];
    const int*   g_idx  = (const int*)  d_in[2];
    const float* gWv11  = (const float*)d_in[3];
    const float* gWv21  = (const float*)d_in[4];
    const float* gWs1   = (const float*)d_in[5];
    const float* gWg1   = (const float*)d_in[6];
    const float* gbg1   = (const float*)d_in[7];
    const float* gWd1   = (const float*)d_in[8];
    const float* gWv12  = (const float*)d_in[9];
    const float* gWs2   = (const float*)d_in[11];
    float* out = (float*)d_out;
    const int M = in_sizes[2];

    const int smem_bytes = SMEM_FLOATS * (int)sizeof(float);  // 232192 B
    cudaFuncSetAttribute(frontier_vn_kernel,
                         cudaFuncAttributeMaxDynamicSharedMemorySize, smem_bytes);

    int sms = 148;
    cudaDeviceGetAttribute(&sms, cudaDevAttrMultiProcessorCount, 0);

    frontier_vn_kernel<<<sms, THREADS, smem_bytes>>>(
        g_sca, g_vec, g_idx,
        gWv11, gWv21, gWs1, gWg1, gbg1, gWd1, gWv12, gWs2,
        out, M);
}

// round 10
// speedup vs baseline: 1.5301x; 1.5301x over previous
#include <cuda_runtime.h>

// ---------------------------------------------------------------------------
// FrontierLayerVN fused kernel, v10 = v5 (best, 679us) + ONE isolated change:
//   Wg1/Wv21/Wd1/Wv12 stored interleaved-transposed in smem so gate/D/E/F
//   read 4 output-column weights with a single LDS.128 (was 4x LDS.32).
//   Stage C is v5's j-halves form (scratch use <= 256 floats; v9's crash was
//   an accidental v4-form gate staging overflowing the 384-float scratch).
// ---------------------------------------------------------------------------

#define NWARPS 12
#define THREADS (NWARPS * 32)
#define FULLMASK 0xffffffffu

#define SZ_WV11 4096   // 64x64
#define SZ_WV21 2048   // 64x32 (interleaved-transposed)
#define SZ_WS1  40960  // 320x128
#define SZ_WG1  4096   // 128x32 (interleaved-transposed)
#define SZ_BG1  32
#define SZ_WD1  1024   // 32x32 (interleaved-transposed)
#define SZ_WV12 1024   // 32x32 (interleaved-transposed)
#define SZ_WS2  160
#define SZ_WEIGHTS (SZ_WV11 + SZ_WV21 + SZ_WS1 + SZ_WG1 + SZ_BG1 + SZ_WD1 + SZ_WV12 + SZ_WS2)
#define WS_FLOATS 384
#define SMEM_FLOATS (SZ_WEIGHTS + NWARPS * WS_FLOATS)   // 58048 floats = 232192 B

typedef unsigned long long u64;

__device__ __forceinline__ u64 pk2(float x, float y) {
    u64 d; asm("mov.b64 %0, {%1, %2};" : "=l"(d) : "f"(x), "f"(y)); return d;
}
__device__ __forceinline__ void upk2(float& x, float& y, u64 d) {
    asm("mov.b64 {%0, %1}, %2;" : "=f"(x), "=f"(y) : "l"(d));
}
__device__ __forceinline__ void fma2(u64& a, u64 x, u64 w) {
    asm("fma.rn.f32x2 %0, %1, %2, %3;" : "=l"(a) : "l"(x), "l"(w), "l"(a));
}
__device__ __forceinline__ float fcomp(const float4& v, int e) {
    return (&v.x)[e];   // e compile-time under #pragma unroll
}

// stage-B inner k-loop over a staged 32-k chunk (layout [r][32] floats)
__device__ __forceinline__ void b_chunk(
    u64* __restrict__ ps01, u64* __restrict__ ps23,
    const float4* __restrict__ wsv4, const float4* __restrict__ sWs1_f4,
    int k_base, int lane)
{
    for (int kq = 0; kq < 8; kq++) {
        float4 xs[8];
        #pragma unroll
        for (int r = 0; r < 8; r++) xs[r] = wsv4[r*8 + kq];
        #pragma unroll
        for (int e = 0; e < 4; e++) {
            int k = k_base + kq*4 + e;
            float4 w = sWs1_f4[k*32 + lane];
            u64 wa = pk2(w.x, w.y), wb = pk2(w.z, w.w);
            #pragma unroll
            for (int r = 0; r < 8; r++) {
                float x = fcomp(xs[r], e);
                u64 xx = pk2(x, x);
                fma2(ps01[r], xx, wa);
                fma2(ps23[r], xx, wb);
            }
        }
    }
}

__global__ __launch_bounds__(THREADS, 1)
void frontier_vn_kernel(
    const float* __restrict__ g_sca,   // (N,256)
    const float* __restrict__ g_vec,   // (N,64,3)
    const int*   __restrict__ g_idx,   // (M,)
    const float* __restrict__ gWv11,   // (64,64)
    const float* __restrict__ gWv21,   // (64,32)
    const float* __restrict__ gWs1,    // (320,128)
    const float* __restrict__ gWg1,    // (128,32)
    const float* __restrict__ gbg1,    // (32,)
    const float* __restrict__ gWd1,    // (32,32)
    const float* __restrict__ gWv12,   // (32,32)
    const float* __restrict__ gWs2,    // (160,)
    float* __restrict__ out,           // (M,)
    int M)
{
    extern __shared__ float sm[];
    float* sWv11 = sm;
    float* sWv21 = sWv11 + SZ_WV11;   // interleaved-transposed
    float* sWs1  = sWv21 + SZ_WV21;
    float* sWg1  = sWs1  + SZ_WS1;    // interleaved-transposed
    float* sbg1  = sWg1  + SZ_WG1;
    float* sWd1  = sbg1  + SZ_BG1;    // interleaved-transposed
    float* sWv12 = sWd1  + SZ_WD1;    // interleaved-transposed
    float* sWs2  = sWv12 + SZ_WV12;
    float* scratch = sWs2 + SZ_WS2;

    const int tid = threadIdx.x;

    // ---- cooperative weight staging ----
    {
        const float4* s; float4* d;
        d = (float4*)sWv11; s = (const float4*)gWv11;
        for (int i = tid; i < SZ_WV11/4; i += THREADS) d[i] = s[i];
        d = (float4*)sWs1;  s = (const float4*)gWs1;
        for (int i = tid; i < SZ_WS1/4;  i += THREADS) d[i] = s[i];
        d = (float4*)sbg1;  s = (const float4*)gbg1;
        for (int i = tid; i < SZ_BG1/4;  i += THREADS) d[i] = s[i];
        d = (float4*)sWs2;  s = (const float4*)gWs2;
        for (int i = tid; i < SZ_WS2/4;  i += THREADS) d[i] = s[i];
        // interleaved-transposed: (k,o) of (K,32) -> float idx (k>>2)*128 + o*4 + (k&3)
        for (int i = tid; i < SZ_WG1; i += THREADS) {
            int k = i >> 5, o = i & 31;
            sWg1[(k >> 2)*128 + (o << 2) + (k & 3)] = gWg1[i];
        }
        for (int i = tid; i < SZ_WV21; i += THREADS) {
            int k = i >> 5, o = i & 31;
            sWv21[(k >> 2)*128 + (o << 2) + (k & 3)] = gWv21[i];
        }
        for (int i = tid; i < SZ_WD1; i += THREADS) {
            int k = i >> 5, o = i & 31;
            sWd1[(k >> 2)*128 + (o << 2) + (k & 3)] = gWd1[i];
        }
        for (int i = tid; i < SZ_WV12; i += THREADS) {
            int k = i >> 5, o = i & 31;
            sWv12[(k >> 2)*128 + (o << 2) + (k & 3)] = gWv12[i];
        }
    }
    __syncthreads();

    const int warp = tid >> 5;
    const int lane = tid & 31;
    float* ws = scratch + warp * WS_FLOATS;
    float4* wsv4 = (float4*)ws;

    const float2* sWv11_f2 = (const float2*)sWv11;
    const float4* sWs1_f4  = (const float4*)sWs1;
    const float4* sWg1_f4  = (const float4*)sWg1;
    const float4* sWv21_f4 = (const float4*)sWv21;
    const float4* sWd1_f4  = (const float4*)sWd1;
    const float4* sWv12_f4 = (const float4*)sWv12;
    const float4* sWs2_f4  = (const float4*)sWs2;
    const float4* g_sca4   = (const float4*)g_sca;
    const float4* g_vec4   = (const float4*)g_vec;

    const int r_ln = lane >> 2;      // row handled by this lane in gathers
    const int q_ln = lane & 3;

    for (int base = (blockIdx.x * NWARPS + warp) * 8; base < M;
         base += gridDim.x * NWARPS * 8)
    {
        int m_dyn = base + r_ln;
        const int idx_dyn = g_idx[(m_dyn < M) ? m_dyn : (M - 1)];
        const size_t vbase = (size_t)idx_dyn * 48;   // f4 units
        const size_t sbase = (size_t)idx_dyn * 64;   // f4 units

        // =================== Stage A: vec -> vh (single pass, R=8) ==========
        u64 pax[8], pay[8], paz[8];
        #pragma unroll
        for (int r = 0; r < 8; r++) { pax[r]=0ull; pay[r]=0ull; paz[r]=0ull; }

        float4 vf0 = g_vec4[vbase + 3*q_ln + 0];
        float4 vf1 = g_vec4[vbase + 3*q_ln + 1];
        float4 vf2 = g_vec4[vbase + 3*q_ln + 2];

        for (int chunk = 0; chunk < 4; chunk++) {
            __syncwarp();
            wsv4[r_ln*12 + 3*q_ln + 0] = vf0;
            wsv4[r_ln*12 + 3*q_ln + 1] = vf1;
            wsv4[r_ln*12 + 3*q_ln + 2] = vf2;
            if (chunk < 3) {
                vf0 = g_vec4[vbase + (chunk+1)*12 + 3*q_ln + 0];
                vf1 = g_vec4[vbase + (chunk+1)*12 + 3*q_ln + 1];
                vf2 = g_vec4[vbase + (chunk+1)*12 + 3*q_ln + 2];
            }
            __syncwarp();
            for (int cq = 0; cq < 4; cq++) {
                u64 ww[4];
                #pragma unroll
                for (int e = 0; e < 4; e++) {
                    float2 w2 = sWv11_f2[(chunk*16 + cq*4 + e)*32 + lane];
                    ww[e] = pk2(w2.x, w2.y);
                }
                #pragma unroll
                for (int r = 0; r < 8; r++) {
                    float4 f0 = wsv4[r*12 + 3*cq + 0];
                    float4 f1 = wsv4[r*12 + 3*cq + 1];
                    float4 f2 = wsv4[r*12 + 3*cq + 2];
                    float vcx[4] = {f0.x, f0.w, f1.z, f2.y};
                    float vcy[4] = {f0.y, f1.x, f1.w, f2.z};
                    float vcz[4] = {f0.z, f1.y, f2.x, f2.w};
                    #pragma unroll
                    for (int e = 0; e < 4; e++) {
                        fma2(pax[r], pk2(vcx[e], vcx[e]), ww[e]);
                        fma2(pay[r], pk2(vcy[e], vcy[e]), ww[e]);
                        fma2(paz[r], pk2(vcz[e], vcz[e]), ww[e]);
                    }
                }
            }
        }

        // =================== Stage B: s1 ====================================
        u64 ps01[8], ps23[8];
        #pragma unroll
        for (int r = 0; r < 8; r++) { ps01[r]=0ull; ps23[r]=0ull; }

        float4 sf0 = g_sca4[sbase + q_ln];
        float4 sf1 = g_sca4[sbase + q_ln + 4];

        // vn passes: k in [0,64), two 32-k chunks; norms computed inline
        #pragma unroll
        for (int chunk = 0; chunk < 2; chunk++) {
            __syncwarp();
            if ((lane >> 4) == chunk) {
                int klocal = 2*lane - 32*chunk;   // even, 0..30
                #pragma unroll
                for (int r = 0; r < 8; r++) {
                    float x0,x1,y0,y1,z0,z1;
                    upk2(x0,x1,pax[r]); upk2(y0,y1,pay[r]); upk2(z0,z1,paz[r]);
                    float2 nn;
                    nn.x = sqrtf(x0*x0 + y0*y0 + z0*z0);
                    nn.y = sqrtf(x1*x1 + y1*y1 + z1*z1);
                    *(float2*)(ws + r*32 + klocal) = nn;
                }
            }
            __syncwarp();
            b_chunk(ps01, ps23, wsv4, sWs1_f4, chunk*32, lane);
        }

        // sca passes: k in [64,320), eight 32-k chunks, staged + prefetched
        for (int pass = 0; pass < 8; pass++) {
            __syncwarp();
            wsv4[r_ln*8 + q_ln]     = sf0;
            wsv4[r_ln*8 + 4 + q_ln] = sf1;
            if (pass < 7) {
                sf0 = g_sca4[sbase + (pass+1)*8 + q_ln];
                sf1 = g_sca4[sbase + (pass+1)*8 + q_ln + 4];
            }
            __syncwarp();
            b_chunk(ps01, ps23, wsv4, sWs1_f4, 64 + pass*32, lane);
        }

        // =================== Stage C: gate (2x 4-row passes, j-halves) ======
        float gg[8];
        #pragma unroll
        for (int p = 0; p < 2; p++) {
            u64 g01 = 0ull, g23 = 0ull;
            #pragma unroll
            for (int half = 0; half < 2; half++) {
                __syncwarp();
                if ((lane >> 4) == half) {
                    int jl = lane & 15;
                    #pragma unroll
                    for (int r2 = 0; r2 < 4; r2++) {
                        float4 sv;
                        upk2(sv.x, sv.y, ps01[p*4+r2]);
                        upk2(sv.z, sv.w, ps23[p*4+r2]);
                        wsv4[r2*16 + jl] = sv;
                    }
                }
                __syncwarp();
                for (int jq = 0; jq < 16; jq++) {
                    float4 x0 = wsv4[0*16 + jq];
                    float4 x1 = wsv4[1*16 + jq];
                    float4 x2 = wsv4[2*16 + jq];
                    float4 x3 = wsv4[3*16 + jq];
                    float4 w4 = sWg1_f4[(half*16 + jq)*32 + lane];
                    #pragma unroll
                    for (int e = 0; e < 4; e++) {
                        float w = fcomp(w4, e);
                        u64 ww = pk2(w, w);
                        fma2(g01, pk2(fcomp(x0,e), fcomp(x1,e)), ww);
                        fma2(g23, pk2(fcomp(x2,e), fcomp(x3,e)), ww);
                    }
                }
            }
            float a,b,c,d;
            upk2(a,b,g01); upk2(c,d,g23);
            float bias = sbg1[lane];
            gg[p*4+0] = 1.f / (1.f + __expf(-(a + bias)));
            gg[p*4+1] = 1.f / (1.f + __expf(-(b + bias)));
            gg[p*4+2] = 1.f / (1.f + __expf(-(c + bias)));
            gg[p*4+3] = 1.f / (1.f + __expf(-(d + bias)));
        }

        // retire ps: fold leaky(s1) . Ws2_tail into per-lane partials
        float partB[8];
        {
            float4 w2tail = sWs2_f4[8 + lane];
            #pragma unroll
            for (int r = 0; r < 8; r++) {
                float s0,s1v,s2,s3;
                upk2(s0,s1v,ps01[r]); upk2(s2,s3,ps23[r]);
                float p = ((s0  >= 0.f) ? s0  : 0.01f*s0)  * w2tail.x;
                p      += ((s1v >= 0.f) ? s1v : 0.01f*s1v) * w2tail.y;
                p      += ((s2  >= 0.f) ? s2  : 0.01f*s2)  * w2tail.z;
                p      += ((s3  >= 0.f) ? s3  : 0.01f*s3)  * w2tail.w;
                partB[r] = p;
            }
        }

        // =================== Stages D/E/F fused per 4-row half ==============
        float w2head = sWs2[lane];
        #pragma unroll
        for (int p = 0; p < 2; p++) {
            // ---- D: out_vec ----
            u64 oxy[4] = {0ull,0ull,0ull,0ull};
            float ozv[4] = {0.f,0.f,0.f,0.f};
            #pragma unroll
            for (int t = 0; t < 2; t++) {
                __syncwarp();
                if ((lane >> 4) == t) {
                    int h0 = 2*lane - 32*t;
                    #pragma unroll
                    for (int r2 = 0; r2 < 4; r2++) {
                        *(u64*)(ws + r2*96 +  0 + h0) = pax[p*4+r2];
                        *(u64*)(ws + r2*96 + 32 + h0) = pay[p*4+r2];
                        *(u64*)(ws + r2*96 + 64 + h0) = paz[p*4+r2];
                    }
                }
                __syncwarp();
                for (int hq = 0; hq < 8; hq++) {
                    float4 xv[4][3];
                    #pragma unroll
                    for (int r2 = 0; r2 < 4; r2++) {
                        xv[r2][0] = wsv4[r2*24 + 0*8 + hq];
                        xv[r2][1] = wsv4[r2*24 + 1*8 + hq];
                        xv[r2][2] = wsv4[r2*24 + 2*8 + hq];
                    }
                    float4 w4 = sWv21_f4[(t*8 + hq)*32 + lane];
                    #pragma unroll
                    for (int e = 0; e < 4; e++) {
                        float w = fcomp(w4, e);
                        u64 ww = pk2(w, w);
                        #pragma unroll
                        for (int r2 = 0; r2 < 4; r2++) {
                            fma2(oxy[r2], pk2(fcomp(xv[r2][0],e), fcomp(xv[r2][1],e)), ww);
                            ozv[r2] += w * fcomp(xv[r2][2], e);
                        }
                    }
                }
            }
            float v2x[4], v2y[4], v2z[4];
            #pragma unroll
            for (int r2 = 0; r2 < 4; r2++) {
                float ox, oy; upk2(ox, oy, oxy[r2]);
                float g = gg[p*4+r2];
                v2x[r2] = g*ox; v2y[r2] = g*oy; v2z[r2] = g*ozv[r2];
            }

            // ---- E: VNLeakyReLU ----
            __syncwarp();
            #pragma unroll
            for (int r2 = 0; r2 < 4; r2++) {
                ws[r2*96 +  0 + lane] = v2x[r2];
                ws[r2*96 + 32 + lane] = v2y[r2];
                ws[r2*96 + 64 + lane] = v2z[r2];
            }
            __syncwarp();
            u64 dxy[4] = {0ull,0ull,0ull,0ull};
            float dzv[4] = {0.f,0.f,0.f,0.f};
            for (int cq = 0; cq < 8; cq++) {
                float4 xv[4][3];
                #pragma unroll
                for (int r2 = 0; r2 < 4; r2++) {
                    xv[r2][0] = wsv4[r2*24 + 0*8 + cq];
                    xv[r2][1] = wsv4[r2*24 + 1*8 + cq];
                    xv[r2][2] = wsv4[r2*24 + 2*8 + cq];
                }
                float4 w4 = sWd1_f4[cq*32 + lane];
                #pragma unroll
                for (int e = 0; e < 4; e++) {
                    float w = fcomp(w4, e);
                    u64 ww = pk2(w, w);
                    #pragma unroll
                    for (int r2 = 0; r2 < 4; r2++) {
                        fma2(dxy[r2], pk2(fcomp(xv[r2][0],e), fcomp(xv[r2][1],e)), ww);
                        dzv[r2] += w * fcomp(xv[r2][2], e);
                    }
                }
            }
            float v3x[4], v3y[4], v3z[4];
            #pragma unroll
            for (int r2 = 0; r2 < 4; r2++) {
                float dx, dy; upk2(dx, dy, dxy[r2]);
                float dz = dzv[r2];
                float dot = v2x[r2]*dx + v2y[r2]*dy + v2z[r2]*dz;
                float dsq = dx*dx + dy*dy + dz*dz;
                float tt  = dot / (dsq + 1e-6f);
                float rx = (dot >= 0.f) ? v2x[r2] : (v2x[r2] - tt*dx);
                float ry = (dot >= 0.f) ? v2y[r2] : (v2y[r2] - tt*dy);
                float rz = (dot >= 0.f) ? v2z[r2] : (v2z[r2] - tt*dz);
                v3x[r2] = 0.2f*v2x[r2] + 0.8f*rx;
                v3y[r2] = 0.2f*v2y[r2] + 0.8f*ry;
                v3z[r2] = 0.2f*v2z[r2] + 0.8f*rz;
            }

            // ---- F: layer 2 + output ----
            __syncwarp();
            #pragma unroll
            for (int r2 = 0; r2 < 4; r2++) {
                ws[r2*96 +  0 + lane] = v3x[r2];
                ws[r2*96 + 32 + lane] = v3y[r2];
                ws[r2*96 + 64 + lane] = v3z[r2];
            }
            __syncwarp();
            u64 bxy[4] = {0ull,0ull,0ull,0ull};
            float bzv[4] = {0.f,0.f,0.f,0.f};
            for (int cq = 0; cq < 8; cq++) {
                float4 xv[4][3];
                #pragma unroll
                for (int r2 = 0; r2 < 4; r2++) {
                    xv[r2][0] = wsv4[r2*24 + 0*8 + cq];
                    xv[r2][1] = wsv4[r2*24 + 1*8 + cq];
                    xv[r2][2] = wsv4[r2*24 + 2*8 + cq];
                }
                float4 w4 = sWv12_f4[cq*32 + lane];
                #pragma unroll
                for (int e = 0; e < 4; e++) {
                    float w = fcomp(w4, e);
                    u64 ww = pk2(w, w);
                    #pragma unroll
                    for (int r2 = 0; r2 < 4; r2++) {
                        fma2(bxy[r2], pk2(fcomp(xv[r2][0],e), fcomp(xv[r2][1],e)), ww);
                        bzv[r2] += w * fcomp(xv[r2][2], e);
                    }
                }
            }
            float res[4];
            #pragma unroll
            for (int r2 = 0; r2 < 4; r2++) {
                float bx, by; upk2(bx, by, bxy[r2]);
                float bz = bzv[r2];
                float vn2 = sqrtf(bx*bx + by*by + bz*bz);
                float pp = vn2 * w2head + partB[p*4+r2];
                #pragma unroll
                for (int off = 16; off > 0; off >>= 1)
                    pp += __shfl_xor_sync(FULLMASK, pp, off);
                res[r2] = pp;
            }
            if (lane == 0) {
                int mb = base + p*4;
                if (mb + 3 < M) {
                    *(float4*)(out + mb) = make_float4(res[0], res[1], res[2], res[3]);
                } else {
                    #pragma unroll
                    for (int r2 = 0; r2 < 4; r2++)
                        if (mb + r2 < M) out[mb + r2] = res[r2];
                }
            }
        }
        __syncwarp();
    }
}

extern "C" void kernel_launch(void* const* d_in, const int* in_sizes, int n_in,
                              void* d_out, int out_size)
{
    const float* g_sca  = (const float*)d_in[0];
    const float* g_vec  = (const float*)d_in[1];
    const int*   g_idx  = (const int*)  d_in[2];
    const float* gWv11  = (const float*)d_in[3];
    const float* gWv21  = (const float*)d_in[4];
    const float* gWs1   = (const float*)d_in[5];
    const float* gWg1   = (const float*)d_in[6];
    const float* gbg1   = (const float*)d_in[7];
    const float* gWd1   = (const float*)d_in[8];
    const float* gWv12  = (const float*)d_in[9];
    const float* gWs2   = (const float*)d_in[11];
    float* out = (float*)d_out;
    const int M = in_sizes[2];

    const int smem_bytes = SMEM_FLOATS * (int)sizeof(float);  // 232192 B
    cudaFuncSetAttribute(frontier_vn_kernel,
                         cudaFuncAttributeMaxDynamicSharedMemorySize, smem_bytes);

    int sms = 148;
    cudaDeviceGetAttribute(&sms, cudaDevAttrMultiProcessorCount, 0);

    frontier_vn_kernel<<<sms, THREADS, smem_bytes>>>(
        g_sca, g_vec, g_idx,
        gWv11, gWv21, gWs1, gWg1, gbg1, gWd1, gWv12, gWs2,
        out, M);
}

// round 11
// speedup vs baseline: 1.5330x; 1.0019x over previous
#include <cuda_runtime.h>

// ---------------------------------------------------------------------------
// FrontierLayerVN fused kernel, v10 = v5 (best, 679us) + ONE isolated change:
//   Wg1/Wv21/Wd1/Wv12 stored interleaved-transposed in smem so gate/D/E/F
//   read 4 output-column weights with a single LDS.128 (was 4x LDS.32).
//   Stage C is v5's j-halves form (scratch use <= 256 floats; v9's crash was
//   an accidental v4-form gate staging overflowing the 384-float scratch).
// ---------------------------------------------------------------------------

#define NWARPS 12
#define THREADS (NWARPS * 32)
#define FULLMASK 0xffffffffu

#define SZ_WV11 4096   // 64x64
#define SZ_WV21 2048   // 64x32 (interleaved-transposed)
#define SZ_WS1  40960  // 320x128
#define SZ_WG1  4096   // 128x32 (interleaved-transposed)
#define SZ_BG1  32
#define SZ_WD1  1024   // 32x32 (interleaved-transposed)
#define SZ_WV12 1024   // 32x32 (interleaved-transposed)
#define SZ_WS2  160
#define SZ_WEIGHTS (SZ_WV11 + SZ_WV21 + SZ_WS1 + SZ_WG1 + SZ_BG1 + SZ_WD1 + SZ_WV12 + SZ_WS2)
#define WS_FLOATS 384
#define SMEM_FLOATS (SZ_WEIGHTS + NWARPS * WS_FLOATS)   // 58048 floats = 232192 B

typedef unsigned long long u64;

__device__ __forceinline__ u64 pk2(float x, float y) {
    u64 d; asm("mov.b64 %0, {%1, %2};" : "=l"(d) : "f"(x), "f"(y)); return d;
}
__device__ __forceinline__ void upk2(float& x, float& y, u64 d) {
    asm("mov.b64 {%0, %1}, %2;" : "=f"(x), "=f"(y) : "l"(d));
}
__device__ __forceinline__ void fma2(u64& a, u64 x, u64 w) {
    asm("fma.rn.f32x2 %0, %1, %2, %3;" : "=l"(a) : "l"(x), "l"(w), "l"(a));
}
__device__ __forceinline__ float fcomp(const float4& v, int e) {
    return (&v.x)[e];   // e compile-time under #pragma unroll
}

// stage-B inner k-loop over a staged 32-k chunk (layout [r][32] floats)
__device__ __forceinline__ void b_chunk(
    u64* __restrict__ ps01, u64* __restrict__ ps23,
    const float4* __restrict__ wsv4, const float4* __restrict__ sWs1_f4,
    int k_base, int lane)
{
    for (int kq = 0; kq < 8; kq++) {
        float4 xs[8];
        #pragma unroll
        for (int r = 0; r < 8; r++) xs[r] = wsv4[r*8 + kq];
        #pragma unroll
        for (int e = 0; e < 4; e++) {
            int k = k_base + kq*4 + e;
            float4 w = sWs1_f4[k*32 + lane];
            u64 wa = pk2(w.x, w.y), wb = pk2(w.z, w.w);
            #pragma unroll
            for (int r = 0; r < 8; r++) {
                float x = fcomp(xs[r], e);
                u64 xx = pk2(x, x);
                fma2(ps01[r], xx, wa);
                fma2(ps23[r], xx, wb);
            }
        }
    }
}

__global__ __launch_bounds__(THREADS, 1)
void frontier_vn_kernel(
    const float* __restrict__ g_sca,   // (N,256)
    const float* __restrict__ g_vec,   // (N,64,3)
    const int*   __restrict__ g_idx,   // (M,)
    const float* __restrict__ gWv11,   // (64,64)
    const float* __restrict__ gWv21,   // (64,32)
    const float* __restrict__ gWs1,    // (320,128)
    const float* __restrict__ gWg1,    // (128,32)
    const float* __restrict__ gbg1,    // (32,)
    const float* __restrict__ gWd1,    // (32,32)
    const float* __restrict__ gWv12,   // (32,32)
    const float* __restrict__ gWs2,    // (160,)
    float* __restrict__ out,           // (M,)
    int M)
{
    extern __shared__ float sm[];
    float* sWv11 = sm;
    float* sWv21 = sWv11 + SZ_WV11;   // interleaved-transposed
    float* sWs1  = sWv21 + SZ_WV21;
    float* sWg1  = sWs1  + SZ_WS1;    // interleaved-transposed
    float* sbg1  = sWg1  + SZ_WG1;
    float* sWd1  = sbg1  + SZ_BG1;    // interleaved-transposed
    float* sWv12 = sWd1  + SZ_WD1;    // interleaved-transposed
    float* sWs2  = sWv12 + SZ_WV12;
    float* scratch = sWs2 + SZ_WS2;

    const int tid = threadIdx.x;

    // ---- cooperative weight staging ----
    {
        const float4* s; float4* d;
        d = (float4*)sWv11; s = (const float4*)gWv11;
        for (int i = tid; i < SZ_WV11/4; i += THREADS) d[i] = s[i];
        d = (float4*)sWs1;  s = (const float4*)gWs1;
        for (int i = tid; i < SZ_WS1/4;  i += THREADS) d[i] = s[i];
        d = (float4*)sbg1;  s = (const float4*)gbg1;
        for (int i = tid; i < SZ_BG1/4;  i += THREADS) d[i] = s[i];
        d = (float4*)sWs2;  s = (const float4*)gWs2;
        for (int i = tid; i < SZ_WS2/4;  i += THREADS) d[i] = s[i];
        // interleaved-transposed: (k,o) of (K,32) -> float idx (k>>2)*128 + o*4 + (k&3)
        for (int i = tid; i < SZ_WG1; i += THREADS) {
            int k = i >> 5, o = i & 31;
            sWg1[(k >> 2)*128 + (o << 2) + (k & 3)] = gWg1[i];
        }
        for (int i = tid; i < SZ_WV21; i += THREADS) {
            int k = i >> 5, o = i & 31;
            sWv21[(k >> 2)*128 + (o << 2) + (k & 3)] = gWv21[i];
        }
        for (int i = tid; i < SZ_WD1; i += THREADS) {
            int k = i >> 5, o = i & 31;
            sWd1[(k >> 2)*128 + (o << 2) + (k & 3)] = gWd1[i];
        }
        for (int i = tid; i < SZ_WV12; i += THREADS) {
            int k = i >> 5, o = i & 31;
            sWv12[(k >> 2)*128 + (o << 2) + (k & 3)] = gWv12[i];
        }
    }
    __syncthreads();

    const int warp = tid >> 5;
    const int lane = tid & 31;
    float* ws = scratch + warp * WS_FLOATS;
    float4* wsv4 = (float4*)ws;

    const float2* sWv11_f2 = (const float2*)sWv11;
    const float4* sWs1_f4  = (const float4*)sWs1;
    const float4* sWg1_f4  = (const float4*)sWg1;
    const float4* sWv21_f4 = (const float4*)sWv21;
    const float4* sWd1_f4  = (const float4*)sWd1;
    const float4* sWv12_f4 = (const float4*)sWv12;
    const float4* sWs2_f4  = (const float4*)sWs2;
    const float4* g_sca4   = (const float4*)g_sca;
    const float4* g_vec4   = (const float4*)g_vec;

    const int r_ln = lane >> 2;      // row handled by this lane in gathers
    const int q_ln = lane & 3;

    for (int base = (blockIdx.x * NWARPS + warp) * 8; base < M;
         base += gridDim.x * NWARPS * 8)
    {
        int m_dyn = base + r_ln;
        const int idx_dyn = g_idx[(m_dyn < M) ? m_dyn : (M - 1)];
        const size_t vbase = (size_t)idx_dyn * 48;   // f4 units
        const size_t sbase = (size_t)idx_dyn * 64;   // f4 units

        // =================== Stage A: vec -> vh (single pass, R=8) ==========
        u64 pax[8], pay[8], paz[8];
        #pragma unroll
        for (int r = 0; r < 8; r++) { pax[r]=0ull; pay[r]=0ull; paz[r]=0ull; }

        float4 vf0 = g_vec4[vbase + 3*q_ln + 0];
        float4 vf1 = g_vec4[vbase + 3*q_ln + 1];
        float4 vf2 = g_vec4[vbase + 3*q_ln + 2];

        for (int chunk = 0; chunk < 4; chunk++) {
            __syncwarp();
            wsv4[r_ln*12 + 3*q_ln + 0] = vf0;
            wsv4[r_ln*12 + 3*q_ln + 1] = vf1;
            wsv4[r_ln*12 + 3*q_ln + 2] = vf2;
            if (chunk < 3) {
                vf0 = g_vec4[vbase + (chunk+1)*12 + 3*q_ln + 0];
                vf1 = g_vec4[vbase + (chunk+1)*12 + 3*q_ln + 1];
                vf2 = g_vec4[vbase + (chunk+1)*12 + 3*q_ln + 2];
            }
            __syncwarp();
            for (int cq = 0; cq < 4; cq++) {
                u64 ww[4];
                #pragma unroll
                for (int e = 0; e < 4; e++) {
                    float2 w2 = sWv11_f2[(chunk*16 + cq*4 + e)*32 + lane];
                    ww[e] = pk2(w2.x, w2.y);
                }
                #pragma unroll
                for (int r = 0; r < 8; r++) {
                    float4 f0 = wsv4[r*12 + 3*cq + 0];
                    float4 f1 = wsv4[r*12 + 3*cq + 1];
                    float4 f2 = wsv4[r*12 + 3*cq + 2];
                    float vcx[4] = {f0.x, f0.w, f1.z, f2.y};
                    float vcy[4] = {f0.y, f1.x, f1.w, f2.z};
                    float vcz[4] = {f0.z, f1.y, f2.x, f2.w};
                    #pragma unroll
                    for (int e = 0; e < 4; e++) {
                        fma2(pax[r], pk2(vcx[e], vcx[e]), ww[e]);
                        fma2(pay[r], pk2(vcy[e], vcy[e]), ww[e]);
                        fma2(paz[r], pk2(vcz[e], vcz[e]), ww[e]);
                    }
                }
            }
        }

        // =================== Stage B: s1 ====================================
        u64 ps01[8], ps23[8];
        #pragma unroll
        for (int r = 0; r < 8; r++) { ps01[r]=0ull; ps23[r]=0ull; }

        float4 sf0 = g_sca4[sbase + q_ln];
        float4 sf1 = g_sca4[sbase + q_ln + 4];

        // vn passes: k in [0,64), two 32-k chunks; norms computed inline
        #pragma unroll
        for (int chunk = 0; chunk < 2; chunk++) {
            __syncwarp();
            if ((lane >> 4) == chunk) {
                int klocal = 2*lane - 32*chunk;   // even, 0..30
                #pragma unroll
                for (int r = 0; r < 8; r++) {
                    float x0,x1,y0,y1,z0,z1;
                    upk2(x0,x1,pax[r]); upk2(y0,y1,pay[r]); upk2(z0,z1,paz[r]);
                    float2 nn;
                    nn.x = sqrtf(x0*x0 + y0*y0 + z0*z0);
                    nn.y = sqrtf(x1*x1 + y1*y1 + z1*z1);
                    *(float2*)(ws + r*32 + klocal) = nn;
                }
            }
            __syncwarp();
            b_chunk(ps01, ps23, wsv4, sWs1_f4, chunk*32, lane);
        }

        // sca passes: k in [64,320), eight 32-k chunks, staged + prefetched
        for (int pass = 0; pass < 8; pass++) {
            __syncwarp();
            wsv4[r_ln*8 + q_ln]     = sf0;
            wsv4[r_ln*8 + 4 + q_ln] = sf1;
            if (pass < 7) {
                sf0 = g_sca4[sbase + (pass+1)*8 + q_ln];
                sf1 = g_sca4[sbase + (pass+1)*8 + q_ln + 4];
            }
            __syncwarp();
            b_chunk(ps01, ps23, wsv4, sWs1_f4, 64 + pass*32, lane);
        }

        // =================== Stage C: gate (2x 4-row passes, j-halves) ======
        float gg[8];
        #pragma unroll
        for (int p = 0; p < 2; p++) {
            u64 g01 = 0ull, g23 = 0ull;
            #pragma unroll
            for (int half = 0; half < 2; half++) {
                __syncwarp();
                if ((lane >> 4) == half) {
                    int jl = lane & 15;
                    #pragma unroll
                    for (int r2 = 0; r2 < 4; r2++) {
                        float4 sv;
                        upk2(sv.x, sv.y, ps01[p*4+r2]);
                        upk2(sv.z, sv.w, ps23[p*4+r2]);
                        wsv4[r2*16 + jl] = sv;
                    }
                }
                __syncwarp();
                for (int jq = 0; jq < 16; jq++) {
                    float4 x0 = wsv4[0*16 + jq];
                    float4 x1 = wsv4[1*16 + jq];
                    float4 x2 = wsv4[2*16 + jq];
                    float4 x3 = wsv4[3*16 + jq];
                    float4 w4 = sWg1_f4[(half*16 + jq)*32 + lane];
                    #pragma unroll
                    for (int e = 0; e < 4; e++) {
                        float w = fcomp(w4, e);
                        u64 ww = pk2(w, w);
                        fma2(g01, pk2(fcomp(x0,e), fcomp(x1,e)), ww);
                        fma2(g23, pk2(fcomp(x2,e), fcomp(x3,e)), ww);
                    }
                }
            }
            float a,b,c,d;
            upk2(a,b,g01); upk2(c,d,g23);
            float bias = sbg1[lane];
            gg[p*4+0] = 1.f / (1.f + __expf(-(a + bias)));
            gg[p*4+1] = 1.f / (1.f + __expf(-(b + bias)));
            gg[p*4+2] = 1.f / (1.f + __expf(-(c + bias)));
            gg[p*4+3] = 1.f / (1.f + __expf(-(d + bias)));
        }

        // retire ps: fold leaky(s1) . Ws2_tail into per-lane partials
        float partB[8];
        {
            float4 w2tail = sWs2_f4[8 + lane];
            #pragma unroll
            for (int r = 0; r < 8; r++) {
                float s0,s1v,s2,s3;
                upk2(s0,s1v,ps01[r]); upk2(s2,s3,ps23[r]);
                float p = ((s0  >= 0.f) ? s0  : 0.01f*s0)  * w2tail.x;
                p      += ((s1v >= 0.f) ? s1v : 0.01f*s1v) * w2tail.y;
                p      += ((s2  >= 0.f) ? s2  : 0.01f*s2)  * w2tail.z;
                p      += ((s3  >= 0.f) ? s3  : 0.01f*s3)  * w2tail.w;
                partB[r] = p;
            }
        }

        // =================== Stages D/E/F fused per 4-row half ==============
        float w2head = sWs2[lane];
        #pragma unroll
        for (int p = 0; p < 2; p++) {
            // ---- D: out_vec ----
            u64 oxy[4] = {0ull,0ull,0ull,0ull};
            float ozv[4] = {0.f,0.f,0.f,0.f};
            #pragma unroll
            for (int t = 0; t < 2; t++) {
                __syncwarp();
                if ((lane >> 4) == t) {
                    int h0 = 2*lane - 32*t;
                    #pragma unroll
                    for (int r2 = 0; r2 < 4; r2++) {
                        *(u64*)(ws + r2*96 +  0 + h0) = pax[p*4+r2];
                        *(u64*)(ws + r2*96 + 32 + h0) = pay[p*4+r2];
                        *(u64*)(ws + r2*96 + 64 + h0) = paz[p*4+r2];
                    }
                }
                __syncwarp();
                for (int hq = 0; hq < 8; hq++) {
                    float4 xv[4][3];
                    #pragma unroll
                    for (int r2 = 0; r2 < 4; r2++) {
                        xv[r2][0] = wsv4[r2*24 + 0*8 + hq];
                        xv[r2][1] = wsv4[r2*24 + 1*8 + hq];
                        xv[r2][2] = wsv4[r2*24 + 2*8 + hq];
                    }
                    float4 w4 = sWv21_f4[(t*8 + hq)*32 + lane];
                    #pragma unroll
                    for (int e = 0; e < 4; e++) {
                        float w = fcomp(w4, e);
                        u64 ww = pk2(w, w);
                        #pragma unroll
                        for (int r2 = 0; r2 < 4; r2++) {
                            fma2(oxy[r2], pk2(fcomp(xv[r2][0],e), fcomp(xv[r2][1],e)), ww);
                            ozv[r2] += w * fcomp(xv[r2][2], e);
                        }
                    }
                }
            }
            float v2x[4], v2y[4], v2z[4];
            #pragma unroll
            for (int r2 = 0; r2 < 4; r2++) {
                float ox, oy; upk2(ox, oy, oxy[r2]);
                float g = gg[p*4+r2];
                v2x[r2] = g*ox; v2y[r2] = g*oy; v2z[r2] = g*ozv[r2];
            }

            // ---- E: VNLeakyReLU ----
            __syncwarp();
            #pragma unroll
            for (int r2 = 0; r2 < 4; r2++) {
                ws[r2*96 +  0 + lane] = v2x[r2];
                ws[r2*96 + 32 + lane] = v2y[r2];
                ws[r2*96 + 64 + lane] = v2z[r2];
            }
            __syncwarp();
            u64 dxy[4] = {0ull,0ull,0ull,0ull};
            float dzv[4] = {0.f,0.f,0.f,0.f};
            for (int cq = 0; cq < 8; cq++) {
                float4 xv[4][3];
                #pragma unroll
                for (int r2 = 0; r2 < 4; r2++) {
                    xv[r2][0] = wsv4[r2*24 + 0*8 + cq];
                    xv[r2][1] = wsv4[r2*24 + 1*8 + cq];
                    xv[r2][2] = wsv4[r2*24 + 2*8 + cq];
                }
                float4 w4 = sWd1_f4[cq*32 + lane];
                #pragma unroll
                for (int e = 0; e < 4; e++) {
                    float w = fcomp(w4, e);
                    u64 ww = pk2(w, w);
                    #pragma unroll
                    for (int r2 = 0; r2 < 4; r2++) {
                        fma2(dxy[r2], pk2(fcomp(xv[r2][0],e), fcomp(xv[r2][1],e)), ww);
                        dzv[r2] += w * fcomp(xv[r2][2], e);
                    }
                }
            }
            float v3x[4], v3y[4], v3z[4];
            #pragma unroll
            for (int r2 = 0; r2 < 4; r2++) {
                float dx, dy; upk2(dx, dy, dxy[r2]);
                float dz = dzv[r2];
                float dot = v2x[r2]*dx + v2y[r2]*dy + v2z[r2]*dz;
                float dsq = dx*dx + dy*dy + dz*dz;
                float tt  = dot / (dsq + 1e-6f);
                float rx = (dot >= 0.f) ? v2x[r2] : (v2x[r2] - tt*dx);
                float ry = (dot >= 0.f) ? v2y[r2] : (v2y[r2] - tt*dy);
                float rz = (dot >= 0.f) ? v2z[r2] : (v2z[r2] - tt*dz);
                v3x[r2] = 0.2f*v2x[r2] + 0.8f*rx;
                v3y[r2] = 0.2f*v2y[r2] + 0.8f*ry;
                v3z[r2] = 0.2f*v2z[r2] + 0.8f*rz;
            }

            // ---- F: layer 2 + output ----
            __syncwarp();
            #pragma unroll
            for (int r2 = 0; r2 < 4; r2++) {
                ws[r2*96 +  0 + lane] = v3x[r2];
                ws[r2*96 + 32 + lane] = v3y[r2];
                ws[r2*96 + 64 + lane] = v3z[r2];
            }
            __syncwarp();
            u64 bxy[4] = {0ull,0ull,0ull,0ull};
            float bzv[4] = {0.f,0.f,0.f,0.f};
            for (int cq = 0; cq < 8; cq++) {
                float4 xv[4][3];
                #pragma unroll
                for (int r2 = 0; r2 < 4; r2++) {
                    xv[r2][0] = wsv4[r2*24 + 0*8 + cq];
                    xv[r2][1] = wsv4[r2*24 + 1*8 + cq];
                    xv[r2][2] = wsv4[r2*24 + 2*8 + cq];
                }
                float4 w4 = sWv12_f4[cq*32 + lane];
                #pragma unroll
                for (int e = 0; e < 4; e++) {
                    float w = fcomp(w4, e);
                    u64 ww = pk2(w, w);
                    #pragma unroll
                    for (int r2 = 0; r2 < 4; r2++) {
                        fma2(bxy[r2], pk2(fcomp(xv[r2][0],e), fcomp(xv[r2][1],e)), ww);
                        bzv[r2] += w * fcomp(xv[r2][2], e);
                    }
                }
            }
            float res[4];
            #pragma unroll
            for (int r2 = 0; r2 < 4; r2++) {
                float bx, by; upk2(bx, by, bxy[r2]);
                float bz = bzv[r2];
                float vn2 = sqrtf(bx*bx + by*by + bz*bz);
                float pp = vn2 * w2head + partB[p*4+r2];
                #pragma unroll
                for (int off = 16; off > 0; off >>= 1)
                    pp += __shfl_xor_sync(FULLMASK, pp, off);
                res[r2] = pp;
            }
            if (lane == 0) {
                int mb = base + p*4;
                if (mb + 3 < M) {
                    *(float4*)(out + mb) = make_float4(res[0], res[1], res[2], res[3]);
                } else {
                    #pragma unroll
                    for (int r2 = 0; r2 < 4; r2++)
                        if (mb + r2 < M) out[mb + r2] = res[r2];
                }
            }
        }
        __syncwarp();
    }
}

extern "C" void kernel_launch(void* const* d_in, const int* in_sizes, int n_in,
                              void* d_out, int out_size)
{
    const float* g_sca  = (const float*)d_in[0];
    const float* g_vec  = (const float*)d_in[1];
    const int*   g_idx  = (const int*)  d_in[2];
    const float* gWv11  = (const float*)d_in[3];
    const float* gWv21  = (const float*)d_in[4];
    const float* gWs1   = (const float*)d_in[5];
    const float* gWg1   = (const float*)d_in[6];
    const float* gbg1   = (const float*)d_in[7];
    const float* gWd1   = (const float*)d_in[8];
    const float* gWv12  = (const float*)d_in[9];
    const float* gWs2   = (const float*)d_in[11];
    float* out = (float*)d_out;
    const int M = in_sizes[2];

    const int smem_bytes = SMEM_FLOATS * (int)sizeof(float);  // 232192 B
    cudaFuncSetAttribute(frontier_vn_kernel,
                         cudaFuncAttributeMaxDynamicSharedMemorySize, smem_bytes);

    int sms = 148;
    cudaDeviceGetAttribute(&sms, cudaDevAttrMultiProcessorCount, 0);

    frontier_vn_kernel<<<sms, THREADS, smem_bytes>>>(
        g_sca, g_vec, g_idx,
        gWv11, gWv21, gWs1, gWg1, gbg1, gWd1, gWv12, gWs2,
        out, M);
}

// round 14
// speedup vs baseline: 1.9602x; 1.2786x over previous
#include <cuda_runtime.h>
#include <cuda_fp16.h>
#include <cstdint>

#define NWARPS 12
#define THREADS 384
#define FULLMASK 0xffffffffu

// ---- smem byte map ----
// [0, 62976)        A-tile fp16 [96 x 320+pad], stride 328 halves (656 B)
//                   after MMA: s1 tile fp32 [96 x 132] (50688 B) -- time-multiplexed
// [62976, 146944)   BT = Ws1^T fp16 [128 x 320+pad], stride 328 halves
// [146944, 196864)  fp32 weights (12480 floats)
// [196864, 215296)  scratch: 12 warps x 384 floats
#define AB_OFF   0
#define A_STRIDE_B 656
#define S1_STRIDE_F 132
#define BT_OFF   62976
#define FW_OFF   146944
#define F_WV11   0
#define F_WV21   4096
#define F_WG1    6144
#define F_BG1    10240
#define F_WD1    10272
#define F_WV12   11296
#define F_WS2    12320
#define SCR_OFF  196864
#define WS_FLOATS 384
#define SMEM_BYTES 215296

typedef unsigned long long u64;
typedef unsigned int u32;

__device__ __forceinline__ u64 pk2(float x, float y){u64 d;asm("mov.b64 %0,{%1,%2};":"=l"(d):"f"(x),"f"(y));return d;}
__device__ __forceinline__ void upk2(float&x,float&y,u64 d){asm("mov.b64 {%0,%1},%2;":"=f"(x),"=f"(y):"l"(d));}
__device__ __forceinline__ void fma2(u64&a,u64 x,u64 w){asm("fma.rn.f32x2 %0,%1,%2,%3;":"=l"(a):"l"(x),"l"(w),"l"(a));}
__device__ __forceinline__ float fcomp(const float4&v,int e){return (&v.x)[e];}

__device__ __forceinline__ u32 smem_u32(const void* p){
    u32 a; asm("{ .reg .u64 t; cvta.to.shared.u64 t, %1; cvt.u32.u64 %0, t; }":"=r"(a):"l"(p)); return a;
}
__device__ __forceinline__ void ldm_x4(u32& r0,u32& r1,u32& r2,u32& r3,u32 addr){
    asm volatile("ldmatrix.sync.aligned.m8n8.x4.shared.b16 {%0,%1,%2,%3}, [%4];"
        : "=r"(r0),"=r"(r1),"=r"(r2),"=r"(r3) : "r"(addr));
}
__device__ __forceinline__ void mma16816(float* c,u32 a0,u32 a1,u32 a2,u32 a3,u32 b0,u32 b1){
    asm volatile("mma.sync.aligned.m16n8k16.row.col.f32.f16.f16.f32 "
        "{%0,%1,%2,%3},{%4,%5,%6,%7},{%8,%9},{%0,%1,%2,%3};"
        : "+f"(c[0]),"+f"(c[1]),"+f"(c[2]),"+f"(c[3])
        : "r"(a0),"r"(a1),"r"(a2),"r"(a3),"r"(b0),"r"(b1));
}

__global__ __launch_bounds__(THREADS, 1)
void frontier_vn_kernel(
    const float* __restrict__ g_sca, const float* __restrict__ g_vec,
    const int* __restrict__ g_idx,
    const float* __restrict__ gWv11, const float* __restrict__ gWv21,
    const float* __restrict__ gWs1,  const float* __restrict__ gWg1,
    const float* __restrict__ gbg1,  const float* __restrict__ gWd1,
    const float* __restrict__ gWv12, const float* __restrict__ gWs2,
    float* __restrict__ out, int M)
{
    extern __shared__ char smc[];
    float* fw    = (float*)(smc + FW_OFF);
    float* sWv11 = fw + F_WV11;
    float* sWv21 = fw + F_WV21;
    float* sWg1  = fw + F_WG1;
    float* sbg1  = fw + F_BG1;
    float* sWd1  = fw + F_WD1;
    float* sWv12 = fw + F_WV12;
    float* sWs2  = fw + F_WS2;
    float* s1f   = (float*)(smc + AB_OFF);

    const int tid = threadIdx.x, warp = tid>>5, lane = tid&31;
    const u32 sbu = smem_u32(smc);

    // ---- one-time init: BT = Ws1^T fp16 (padded stride), fp32 weights ----
    for (int i = tid; i < 40960; i += THREADS) {
        int k = i >> 7, j = i & 127;
        *(__half*)(smc + BT_OFF + j*A_STRIDE_B + k*2) = __float2half(gWs1[i]);
    }
    {
        float4* d; const float4* s;
        d=(float4*)sWv11; s=(const float4*)gWv11; for(int i=tid;i<1024;i+=THREADS) d[i]=s[i];
        d=(float4*)sWv21; s=(const float4*)gWv21; for(int i=tid;i<512; i+=THREADS) d[i]=s[i];
        d=(float4*)sWg1;  s=(const float4*)gWg1;  for(int i=tid;i<1024;i+=THREADS) d[i]=s[i];
        d=(float4*)sbg1;  s=(const float4*)gbg1;  for(int i=tid;i<8;   i+=THREADS) d[i]=s[i];
        d=(float4*)sWd1;  s=(const float4*)gWd1;  for(int i=tid;i<256; i+=THREADS) d[i]=s[i];
        d=(float4*)sWv12; s=(const float4*)gWv12; for(int i=tid;i<256; i+=THREADS) d[i]=s[i];
        d=(float4*)sWs2;  s=(const float4*)gWs2;  for(int i=tid;i<40;  i+=THREADS) d[i]=s[i];
    }
    __syncthreads();

    float* ws = (float*)(smc + SCR_OFF) + warp * WS_FLOATS;
    float4* wsv4 = (float4*)ws;
    const float2* sWv11_f2 = (const float2*)sWv11;
    const float4* g_sca4 = (const float4*)g_sca;
    const float4* g_vec4 = (const float4*)g_vec;

    const int r_ln = lane >> 2, q_ln = lane & 3;
    const int pblk = warp >> 1;      // 16-row block
    const int jhalf = warp & 1;      // 64-col half
    const float w2head = sWs2[lane];

    // per-lane ldmatrix base addresses (row layouts per m16n8k16 fragments)
    const u32 a_base = sbu + AB_OFF
        + (u32)(pblk*16 + (lane&7) + ((lane>>3)&1)*8) * A_STRIDE_B
        + (u32)(lane>>4) * 16;
    const u32 b_base = sbu + BT_OFF
        + (u32)(jhalf*64 + (lane&7) + (lane>>4)*8) * A_STRIDE_B
        + (u32)((lane>>3)&1) * 16;

    for (int tile = blockIdx.x * 96; tile < M; tile += gridDim.x * 96)
    {
        const int base = tile + warp * 8;
        int m_dyn = base + r_ln;
        const int idx_dyn = g_idx[(m_dyn < M) ? m_dyn : (M - 1)];
        const size_t vbase = (size_t)idx_dyn * 48;
        const size_t sbase = (size_t)idx_dyn * 64;

        // ===== Stage A (v5): vec -> vh in registers =====
        u64 pax[8], pay[8], paz[8];
        #pragma unroll
        for (int r = 0; r < 8; r++) { pax[r]=0ull; pay[r]=0ull; paz[r]=0ull; }
        float4 vf0 = g_vec4[vbase + 3*q_ln + 0];
        float4 vf1 = g_vec4[vbase + 3*q_ln + 1];
        float4 vf2 = g_vec4[vbase + 3*q_ln + 2];
        for (int chunk = 0; chunk < 4; chunk++) {
            __syncwarp();
            wsv4[r_ln*12 + 3*q_ln + 0] = vf0;
            wsv4[r_ln*12 + 3*q_ln + 1] = vf1;
            wsv4[r_ln*12 + 3*q_ln + 2] = vf2;
            if (chunk < 3) {
                vf0 = g_vec4[vbase + (chunk+1)*12 + 3*q_ln + 0];
                vf1 = g_vec4[vbase + (chunk+1)*12 + 3*q_ln + 1];
                vf2 = g_vec4[vbase + (chunk+1)*12 + 3*q_ln + 2];
            }
            __syncwarp();
            for (int cq = 0; cq < 4; cq++) {
                u64 ww[4];
                #pragma unroll
                for (int e = 0; e < 4; e++) {
                    float2 w2 = sWv11_f2[(chunk*16 + cq*4 + e)*32 + lane];
                    ww[e] = pk2(w2.x, w2.y);
                }
                #pragma unroll
                for (int r = 0; r < 8; r++) {
                    float4 f0 = wsv4[r*12 + 3*cq + 0];
                    float4 f1 = wsv4[r*12 + 3*cq + 1];
                    float4 f2 = wsv4[r*12 + 3*cq + 2];
                    float vcx[4] = {f0.x, f0.w, f1.z, f2.y};
                    float vcy[4] = {f0.y, f1.x, f1.w, f2.z};
                    float vcz[4] = {f0.z, f1.y, f2.x, f2.w};
                    #pragma unroll
                    for (int e = 0; e < 4; e++) {
                        fma2(pax[r], pk2(vcx[e], vcx[e]), ww[e]);
                        fma2(pay[r], pk2(vcy[e], vcy[e]), ww[e]);
                        fma2(paz[r], pk2(vcz[e], vcz[e]), ww[e]);
                    }
                }
            }
        }

        // ===== A-tile staging (fp16, row-major, stride 656 B) =====
        #pragma unroll
        for (int r = 0; r < 8; r++) {
            float x0,x1,y0,y1,z0,z1;
            upk2(x0,x1,pax[r]); upk2(y0,y1,pay[r]); upk2(z0,z1,paz[r]);
            __half2 nn = __floats2half2_rn(sqrtf(x0*x0+y0*y0+z0*z0),
                                           sqrtf(x1*x1+y1*y1+z1*z1));
            *(__half2*)(smc + (warp*8 + r)*A_STRIDE_B + lane*4) = nn;
        }
        {
            const int mrow = warp*8 + r_ln;
            #pragma unroll
            for (int pass = 0; pass < 8; pass++) {
                float4 a = g_sca4[sbase + pass*8 + q_ln*2];
                float4 b = g_sca4[sbase + pass*8 + q_ln*2 + 1];
                __half2 h0 = __floats2half2_rn(a.x, a.y);
                __half2 h1 = __floats2half2_rn(a.z, a.w);
                __half2 h2 = __floats2half2_rn(b.x, b.y);
                __half2 h3 = __floats2half2_rn(b.z, b.w);
                uint4 v;
                v.x = *(u32*)&h0; v.y = *(u32*)&h1;
                v.z = *(u32*)&h2; v.w = *(u32*)&h3;
                *(uint4*)(smc + mrow*A_STRIDE_B + 128 + pass*64 + q_ln*16) = v;
            }
        }
        __syncthreads();

        // ===== Stage B: HMMA, warp computes rows [pblk*16,+16) x cols [jhalf*64,+64) =====
        float cacc[32];
        #pragma unroll
        for (int i = 0; i < 32; i++) cacc[i] = 0.f;
        #pragma unroll
        for (int ks = 0; ks < 20; ks++) {
            u32 a0,a1,a2,a3;
            ldm_x4(a0,a1,a2,a3, a_base + ks*32);
            #pragma unroll
            for (int jb2 = 0; jb2 < 4; jb2++) {
                u32 b0,b1,b2,b3;
                ldm_x4(b0,b1,b2,b3, b_base + jb2*(16*A_STRIDE_B) + ks*32);
                mma16816(cacc + (jb2*2+0)*4, a0,a1,a2,a3, b0,b1);
                mma16816(cacc + (jb2*2+1)*4, a0,a1,a2,a3, b2,b3);
            }
        }
        __syncthreads();   // all ldmatrix reads of A-tile done before s1 overwrites it

        // ===== write s1 (fp32) into the A region =====
        {
            int row0 = pblk*16 + (lane>>2);
            int colb = jhalf*64 + 2*(lane&3);
            #pragma unroll
            for (int jb = 0; jb < 8; jb++) {
                float* p0 = s1f + row0*S1_STRIDE_F + colb + jb*8;
                float* p1 = s1f + (row0+8)*S1_STRIDE_F + colb + jb*8;
                *(float2*)p0 = make_float2(cacc[jb*4+0], cacc[jb*4+1]);
                *(float2*)p1 = make_float2(cacc[jb*4+2], cacc[jb*4+3]);
            }
        }
        __syncthreads();

        // ===== Gate (v5 structure, reading s1 tile) =====
        float ggf[8];
        #pragma unroll
        for (int p2 = 0; p2 < 2; p2++) {
            u64 g01 = 0ull, g23 = 0ull;
            const float4* r0p = (const float4*)(s1f + (warp*8 + p2*4 + 0)*S1_STRIDE_F);
            const float4* r1p = (const float4*)(s1f + (warp*8 + p2*4 + 1)*S1_STRIDE_F);
            const float4* r2p = (const float4*)(s1f + (warp*8 + p2*4 + 2)*S1_STRIDE_F);
            const float4* r3p = (const float4*)(s1f + (warp*8 + p2*4 + 3)*S1_STRIDE_F);
            for (int jq = 0; jq < 32; jq++) {
                float4 x0 = r0p[jq];
                float4 x1 = r1p[jq];
                float4 x2 = r2p[jq];
                float4 x3 = r3p[jq];
                #pragma unroll
                for (int e = 0; e < 4; e++) {
                    float w = sWg1[(jq*4 + e)*32 + lane];
                    u64 ww = pk2(w, w);
                    fma2(g01, pk2(fcomp(x0,e), fcomp(x1,e)), ww);
                    fma2(g23, pk2(fcomp(x2,e), fcomp(x3,e)), ww);
                }
            }
            float a,b,c,d;
            upk2(a,b,g01); upk2(c,d,g23);
            float bias = sbg1[lane];
            ggf[p2*4+0] = 1.f/(1.f+__expf(-(a+bias)));
            ggf[p2*4+1] = 1.f/(1.f+__expf(-(b+bias)));
            ggf[p2*4+2] = 1.f/(1.f+__expf(-(c+bias)));
            ggf[p2*4+3] = 1.f/(1.f+__expf(-(d+bias)));
        }

        // ===== partB: lane handles row r_ln, j-slice q_ln*32..+32 =====
        float partBv = 0.f;
        {
            const float4* sp = (const float4*)(s1f + (warp*8 + r_ln)*S1_STRIDE_F) + q_ln*8;
            const float4* wt = (const float4*)(sWs2 + 32) + q_ln*8;
            #pragma unroll
            for (int i = 0; i < 8; i++) {
                float4 sv = sp[i], w = wt[i];
                partBv += ((sv.x>=0.f)?sv.x:0.01f*sv.x)*w.x
                        + ((sv.y>=0.f)?sv.y:0.01f*sv.y)*w.y
                        + ((sv.z>=0.f)?sv.z:0.01f*sv.z)*w.z
                        + ((sv.w>=0.f)?sv.w:0.01f*sv.w)*w.w;
            }
        }

        // ===== Stages D/E/F (v5) =====
        #pragma unroll
        for (int p = 0; p < 2; p++) {
            u64 oxy[4] = {0ull,0ull,0ull,0ull};
            float ozv[4] = {0.f,0.f,0.f,0.f};
            #pragma unroll
            for (int t = 0; t < 2; t++) {
                __syncwarp();
                if ((lane >> 4) == t) {
                    int h0 = 2*lane - 32*t;
                    #pragma unroll
                    for (int r2 = 0; r2 < 4; r2++) {
                        *(u64*)(ws + r2*96 +  0 + h0) = pax[p*4+r2];
                        *(u64*)(ws + r2*96 + 32 + h0) = pay[p*4+r2];
                        *(u64*)(ws + r2*96 + 64 + h0) = paz[p*4+r2];
                    }
                }
                __syncwarp();
                for (int hq = 0; hq < 8; hq++) {
                    float4 xv[4][3];
                    #pragma unroll
                    for (int r2 = 0; r2 < 4; r2++) {
                        xv[r2][0] = wsv4[r2*24 + 0*8 + hq];
                        xv[r2][1] = wsv4[r2*24 + 1*8 + hq];
                        xv[r2][2] = wsv4[r2*24 + 2*8 + hq];
                    }
                    #pragma unroll
                    for (int e = 0; e < 4; e++) {
                        float w = sWv21[(t*32 + hq*4 + e)*32 + lane];
                        u64 ww = pk2(w, w);
                        #pragma unroll
                        for (int r2 = 0; r2 < 4; r2++) {
                            fma2(oxy[r2], pk2(fcomp(xv[r2][0],e), fcomp(xv[r2][1],e)), ww);
                            ozv[r2] += w * fcomp(xv[r2][2], e);
                        }
                    }
                }
            }
            float v2x[4], v2y[4], v2z[4];
            #pragma unroll
            for (int r2 = 0; r2 < 4; r2++) {
                float ox, oy; upk2(ox, oy, oxy[r2]);
                float g = ggf[p*4+r2];
                v2x[r2] = g*ox; v2y[r2] = g*oy; v2z[r2] = g*ozv[r2];
            }
            __syncwarp();
            #pragma unroll
            for (int r2 = 0; r2 < 4; r2++) {
                ws[r2*96 +  0 + lane] = v2x[r2];
                ws[r2*96 + 32 + lane] = v2y[r2];
                ws[r2*96 + 64 + lane] = v2z[r2];
            }
            __syncwarp();
            u64 dxy[4] = {0ull,0ull,0ull,0ull};
            float dzv[4] = {0.f,0.f,0.f,0.f};
            for (int cq = 0; cq < 8; cq++) {
                float4 xv[4][3];
                #pragma unroll
                for (int r2 = 0; r2 < 4; r2++) {
                    xv[r2][0] = wsv4[r2*24 + 0*8 + cq];
                    xv[r2][1] = wsv4[r2*24 + 1*8 + cq];
                    xv[r2][2] = wsv4[r2*24 + 2*8 + cq];
                }
                #pragma unroll
                for (int e = 0; e < 4; e++) {
                    float w = sWd1[(cq*4 + e)*32 + lane];
                    u64 ww = pk2(w, w);
                    #pragma unroll
                    for (int r2 = 0; r2 < 4; r2++) {
                        fma2(dxy[r2], pk2(fcomp(xv[r2][0],e), fcomp(xv[r2][1],e)), ww);
                        dzv[r2] += w * fcomp(xv[r2][2], e);
                    }
                }
            }
            float v3x[4], v3y[4], v3z[4];
            #pragma unroll
            for (int r2 = 0; r2 < 4; r2++) {
                float dx, dy; upk2(dx, dy, dxy[r2]);
                float dz = dzv[r2];
                float dot = v2x[r2]*dx + v2y[r2]*dy + v2z[r2]*dz;
                float dsq = dx*dx + dy*dy + dz*dz;
                float tt  = dot / (dsq + 1e-6f);
                float rx = (dot >= 0.f) ? v2x[r2] : (v2x[r2] - tt*dx);
                float ry = (dot >= 0.f) ? v2y[r2] : (v2y[r2] - tt*dy);
                float rz = (dot >= 0.f) ? v2z[r2] : (v2z[r2] - tt*dz);
                v3x[r2] = 0.2f*v2x[r2] + 0.8f*rx;
                v3y[r2] = 0.2f*v2y[r2] + 0.8f*ry;
                v3z[r2] = 0.2f*v2z[r2] + 0.8f*rz;
            }
            __syncwarp();
            #pragma unroll
            for (int r2 = 0; r2 < 4; r2++) {
                ws[r2*96 +  0 + lane] = v3x[r2];
                ws[r2*96 + 32 + lane] = v3y[r2];
                ws[r2*96 + 64 + lane] = v3z[r2];
            }
            __syncwarp();
            u64 bxy[4] = {0ull,0ull,0ull,0ull};
            float bzv[4] = {0.f,0.f,0.f,0.f};
            for (int cq = 0; cq < 8; cq++) {
                float4 xv[4][3];
                #pragma unroll
                for (int r2 = 0; r2 < 4; r2++) {
                    xv[r2][0] = wsv4[r2*24 + 0*8 + cq];
                    xv[r2][1] = wsv4[r2*24 + 1*8 + cq];
                    xv[r2][2] = wsv4[r2*24 + 2*8 + cq];
                }
                #pragma unroll
                for (int e = 0; e < 4; e++) {
                    float w = sWv12[(cq*4 + e)*32 + lane];
                    u64 ww = pk2(w, w);
                    #pragma unroll
                    for (int r2 = 0; r2 < 4; r2++) {
                        fma2(bxy[r2], pk2(fcomp(xv[r2][0],e), fcomp(xv[r2][1],e)), ww);
                        bzv[r2] += w * fcomp(xv[r2][2], e);
                    }
                }
            }
            float res[4];
            #pragma unroll
            for (int r2 = 0; r2 < 4; r2++) {
                float bx, by; upk2(bx, by, bxy[r2]);
                float bz = bzv[r2];
                float vn2 = sqrtf(bx*bx + by*by + bz*bz);
                float pb = ((lane>>2) == (p*4+r2)) ? partBv : 0.f;
                float pp = vn2 * w2head + pb;
                #pragma unroll
                for (int off = 16; off > 0; off >>= 1)
                    pp += __shfl_xor_sync(FULLMASK, pp, off);
                res[r2] = pp;
            }
            if (lane == 0) {
                int mb = base + p*4;
                if (mb + 3 < M) {
                    *(float4*)(out + mb) = make_float4(res[0], res[1], res[2], res[3]);
                } else {
                    #pragma unroll
                    for (int r2 = 0; r2 < 4; r2++)
                        if (mb + r2 < M) out[mb + r2] = res[r2];
                }
            }
        }
        __syncthreads();   // all warps done reading s1 tile before next tile's A staging
    }
}

extern "C" void kernel_launch(void* const* d_in, const int* in_sizes, int n_in,
                              void* d_out, int out_size)
{
    const float* g_sca  = (const float*)d_in[0];
    const float* g_vec  = (const float*)d_in[1];
    const int*   g_idx  = (const int*)  d_in[2];
    const float* gWv11  = (const float*)d_in[3];
    const float* gWv21  = (const float*)d_in[4];
    const float* gWs1   = (const float*)d_in[5];
    const float* gWg1   = (const float*)d_in[6];
    const float* gbg1   = (const float*)d_in[7];
    const float* gWd1   = (const float*)d_in[8];
    const float* gWv12  = (const float*)d_in[9];
    const float* gWs2   = (const float*)d_in[11];
    float* out = (float*)d_out;
    const int M = in_sizes[2];

    cudaFuncSetAttribute(frontier_vn_kernel,
                         cudaFuncAttributeMaxDynamicSharedMemorySize, SMEM_BYTES);
    int sms = 148;
    cudaDeviceGetAttribute(&sms, cudaDevAttrMultiProcessorCount, 0);

    frontier_vn_kernel<<<sms, THREADS, SMEM_BYTES>>>(
        g_sca, g_vec, g_idx,
        gWv11, gWv21, gWs1, gWg1, gbg1, gWd1, gWv12, gWs2,
        out, M);
}